// round 5
// baseline (speedup 1.0000x reference)
#include <cuda_runtime.h>
#include <cuda_bf16.h>

#define BATCH 512
#define NTOK  4096
#define NP1   4097
#define NTHR  128

#define CONTENT_PAD 1024
#define CONTENT_EOS 1025
#define COARSE_POS_PAD 128
#define COARSE_POS_EOS 129
#define MEDIUM_POS_PAD 256
#define MEDIUM_POS_EOS 257
#define FINE_POS_PAD 1024
#define FINE_POS_EOS 1025

// Output: 9 sections, each [BATCH, NP1] float32, concatenated in tuple order:
//  0 coarse_content, 1 medium_content, 2 fine_content,
//  3 coarse_position, 4 medium_position, 5 fine_position,
//  6 coarse_segment,  7 medium_segment,  8 fine_segment
__global__ __launch_bounds__(NTHR)
void triple_grain_kernel(const int* __restrict__ in0,
                         const int* __restrict__ in1,
                         float* __restrict__ out)
{
    __shared__ int sA[NTOK];     // row of in0
    __shared__ int sB[NTOK];     // row of in1
    __shared__ int scnt[3];
    __shared__ int sflag;        // 1 if in0 is grain

    const int b = blockIdx.x;
    const int t = threadIdx.x;
    const unsigned lane = t & 31u;
    const unsigned warp = t >> 5;

    // ---- cooperative load of both rows (vectorized, coalesced) ----
    const int4* a4 = (const int4*)(in0 + (long)b * NTOK);
    const int4* b4 = (const int4*)(in1 + (long)b * NTOK);
    int amax = 0;
    for (int i = t; i < NTOK / 4; i += NTHR) {
        int4 va = a4[i];
        int4 vb = b4[i];
        ((int4*)sA)[i] = va;
        ((int4*)sB)[i] = vb;
        amax = max(amax, max(max(va.x, va.y), max(va.z, va.w)));
    }
    // block max of in0 decides which input is grain (grain values are <= 2)
#pragma unroll
    for (int d = 16; d > 0; d >>= 1)
        amax = max(amax, __shfl_xor_sync(0xffffffffu, amax, d));
    __shared__ int smax[4];
    if (lane == 0) smax[warp] = amax;
    __syncthreads();
    if (t == 0) {
        int m = max(max(smax[0], smax[1]), max(smax[2], smax[3]));
        sflag = (m <= 2) ? 1 : 0;
    }
    __syncthreads();

    const int* gs = sflag ? sA : sB;   // grain row in smem
    const int* vs = sflag ? sB : sA;   // content row in smem

    // ---- section base pointers for this row ----
    const long plane = (long)BATCH * NP1;
    const long rowb  = (long)b * NP1;
    float* cc  = out + 0 * plane + rowb;
    float* mc  = out + 1 * plane + rowb;
    float* fc  = out + 2 * plane + rowb;
    float* cp  = out + 3 * plane + rowb;
    float* mp  = out + 4 * plane + rowb;
    float* fp_ = out + 5 * plane + rowb;
    float* cs  = out + 6 * plane + rowb;
    float* ms  = out + 7 * plane + rowb;
    float* fs  = out + 8 * plane + rowb;

    // ---- warp 0: sequential ballot compaction (stable by construction) ----
    if (warp == 0) {
        int off0 = 0, off1 = 0, off2 = 0;
        const unsigned ltmask = (1u << lane) - 1u;
#pragma unroll 4
        for (int chunk = 0; chunk < NTOK / 32; chunk++) {
            const int idx = chunk * 32 + (int)lane;
            const int g = gs[idx];
            const float v = (float)vs[idx];
            const float p = (float)idx;
            const unsigned b0 = __ballot_sync(0xffffffffu, g == 0);
            const unsigned b1 = __ballot_sync(0xffffffffu, g == 1);
            const unsigned b2 = __ballot_sync(0xffffffffu, g == 2);
            if (g == 0) {
                const int r = off0 + __popc(b0 & ltmask);
                cc[r] = v; cp[r] = p;
            } else if (g == 1) {
                const int r = off1 + __popc(b1 & ltmask);
                mc[r] = v; mp[r] = p;
            } else {
                const int r = off2 + __popc(b2 & ltmask);
                fc[r] = v; fp_[r] = p;
            }
            off0 += __popc(b0);
            off1 += __popc(b1);
            off2 += __popc(b2);
        }
        if (lane == 0) {
            scnt[0] = off0;
            scnt[1] = off1;
            scnt[2] = off2;
        }
    }
    __syncthreads();

    const int cnt0 = scnt[0];
    const int cnt1 = scnt[1];
    const int cnt2 = scnt[2];

    // ---- EOS + PAD tails (slot cnt = EOS, slots > cnt = PAD) ----
    for (int j = cnt0 + t; j < NP1; j += NTHR) {
        cc[j] = (j == cnt0) ? (float)CONTENT_EOS    : (float)CONTENT_PAD;
        cp[j] = (j == cnt0) ? (float)COARSE_POS_EOS : (float)COARSE_POS_PAD;
    }
    for (int j = cnt1 + t; j < NP1; j += NTHR) {
        mc[j] = (j == cnt1) ? (float)CONTENT_EOS    : (float)CONTENT_PAD;
        mp[j] = (j == cnt1) ? (float)MEDIUM_POS_EOS : (float)MEDIUM_POS_PAD;
    }
    for (int j = cnt2 + t; j < NP1; j += NTHR) {
        fc[j]  = (j == cnt2) ? (float)CONTENT_EOS  : (float)CONTENT_PAD;
        fp_[j] = (j == cnt2) ? (float)FINE_POS_EOS : (float)FINE_POS_PAD;
    }

    // ---- constant segment planes ----
    for (int j = t; j < NP1; j += NTHR) {
        cs[j] = 0.0f;
        ms[j] = 1.0f;
        fs[j] = 2.0f;
    }
}

extern "C" void kernel_launch(void* const* d_in, const int* in_sizes, int n_in,
                              void* d_out, int out_size)
{
    const int* in0 = (const int*)d_in[0];
    const int* in1 = (const int*)d_in[1];
    float* out = (float*)d_out;
    triple_grain_kernel<<<BATCH, NTHR>>>(in0, in1, out);
}

// round 7
// speedup vs baseline: 1.4072x; 1.4072x over previous
#include <cuda_runtime.h>
#include <cuda_bf16.h>

#define BATCH 512
#define NTOK  4096
#define NP1   4097
#define NTHR  512

#define CONTENT_PAD 1024.0f
#define CONTENT_EOS 1025.0f
#define COARSE_POS_PAD 128.0f
#define COARSE_POS_EOS 129.0f
#define MEDIUM_POS_PAD 256.0f
#define MEDIUM_POS_EOS 257.0f
#define FINE_POS_PAD 1024.0f
#define FINE_POS_EOS 1025.0f

// Fill indices [cnt, NP1): EOS at cnt, PAD beyond. Row's global element
// offset is congruent to b_align (mod 4); vector stores aligned accordingly.
__device__ __forceinline__ void fill_tail(float* __restrict__ ptr, int cnt,
                                          float eos, float pad,
                                          int t, int b_align)
{
    if (t == 0) ptr[cnt] = eos;
    const int start = cnt + 1;
    int vstart = start + ((4 - ((start + b_align) & 3)) & 3);
    if (vstart > NP1) vstart = NP1;
    for (int j = start + t; j < vstart; j += NTHR) ptr[j] = pad;       // <=3 elems
    const int nvec = (NP1 - vstart) >> 2;
    const float4 p4 = make_float4(pad, pad, pad, pad);
    float4* vp = (float4*)(ptr + vstart);
    for (int c = t; c < nvec; c += NTHR) vp[c] = p4;
    const int tail = vstart + (nvec << 2);
    for (int j = tail + t; j < NP1; j += NTHR) ptr[j] = pad;           // <=3 elems
}

// Fill whole row [0, NP1) with a constant.
__device__ __forceinline__ void fill_const(float* __restrict__ ptr, float val,
                                           int t, int b_align)
{
    const int vstart = (4 - (b_align & 3)) & 3;
    for (int j = t; j < vstart; j += NTHR) ptr[j] = val;
    const int nvec = (NP1 - vstart) >> 2;
    const float4 p4 = make_float4(val, val, val, val);
    float4* vp = (float4*)(ptr + vstart);
    for (int c = t; c < nvec; c += NTHR) vp[c] = p4;
    const int tail = vstart + (nvec << 2);
    for (int j = tail + t; j < NP1; j += NTHR) ptr[j] = val;
}

// Output: 9 sections, each [BATCH, NP1] float32, in tuple order:
//  0 coarse_content, 1 medium_content, 2 fine_content,
//  3 coarse_position, 4 medium_position, 5 fine_position,
//  6 coarse_segment,  7 medium_segment,  8 fine_segment
__global__ __launch_bounds__(NTHR)
void triple_grain_kernel(const int* __restrict__ in0,
                         const int* __restrict__ in1,
                         float* __restrict__ out)
{
    const int b = blockIdx.x;
    const int t = threadIdx.x;
    const unsigned lane = t & 31u;
    const unsigned warp = t >> 5;

    // ---- load 8 values from each input (vectorized, register-resident) ----
    const int4* a4 = (const int4*)(in0 + (long)b * NTOK);
    const int4* b4 = (const int4*)(in1 + (long)b * NTOK);
    int4 aa = a4[t * 2 + 0];
    int4 ab = a4[t * 2 + 1];
    int4 ba = b4[t * 2 + 0];
    int4 bb = b4[t * 2 + 1];
    int av[8] = {aa.x, aa.y, aa.z, aa.w, ab.x, ab.y, ab.z, ab.w};
    int bv[8] = {ba.x, ba.y, ba.z, ba.w, bb.x, bb.y, bb.z, bb.w};

    // ---- which input is grain? (grain row max <= 2) ----
    int amax = av[0];
#pragma unroll
    for (int i = 1; i < 8; i++) amax = max(amax, av[i]);
#pragma unroll
    for (int d = 16; d > 0; d >>= 1)
        amax = max(amax, __shfl_xor_sync(0xffffffffu, amax, d));

    __shared__ int smax[16];
    __shared__ int s_a_is_grain;
    if (lane == 0) smax[warp] = amax;
    __syncthreads();
    if (t == 0) {
        int m = smax[0];
#pragma unroll
        for (int i = 1; i < 16; i++) m = max(m, smax[i]);
        s_a_is_grain = (m <= 2) ? 1 : 0;
    }
    __syncthreads();
    const bool a_is_grain = (s_a_is_grain != 0);

    int gv[8], iv[8];
#pragma unroll
    for (int i = 0; i < 8; i++) {
        gv[i] = a_is_grain ? av[i] : bv[i];
        iv[i] = a_is_grain ? bv[i] : av[i];
    }

    // ---- per-thread counts of class 0 / class 1 (class 2 derived) ----
    unsigned c0 = 0, c1 = 0;
#pragma unroll
    for (int i = 0; i < 8; i++) {
        c0 += (gv[i] == 0);
        c1 += (gv[i] == 1);
    }
    const unsigned packed = c0 | (c1 << 16);   // sums <= 4096, no carry

    // ---- block-wide exclusive scan of packed (16 warps) ----
    unsigned inc = packed;
#pragma unroll
    for (int d = 1; d < 32; d <<= 1) {
        unsigned n = __shfl_up_sync(0xffffffffu, inc, d);
        if (lane >= (unsigned)d) inc += n;
    }

    __shared__ unsigned warp_sums[16];
    __shared__ unsigned block_total;
    if (lane == 31) warp_sums[warp] = inc;
    __syncthreads();

    if (warp == 0 && lane < 16) {
        unsigned w = warp_sums[lane];
        unsigned wi = w;
#pragma unroll
        for (int d = 1; d < 16; d <<= 1) {
            unsigned n = __shfl_up_sync(0xffffu, wi, d);
            if (lane >= (unsigned)d) wi += n;
        }
        warp_sums[lane] = wi - w;               // exclusive warp offset
        if (lane == 15) block_total = wi;
    }
    __syncthreads();

    const unsigned ex = warp_sums[warp] + (inc - packed);  // thread-exclusive
    const unsigned tot = block_total;

    const int cnt0 = (int)(tot & 0xFFFFu);
    const int cnt1 = (int)(tot >> 16);
    const int cnt2 = NTOK - cnt0 - cnt1;

    int off0 = (int)(ex & 0xFFFFu);
    int off1 = (int)(ex >> 16);
    int off2 = 8 * t - off0 - off1;

    // ---- section base pointers for this row ----
    const long plane = (long)BATCH * NP1;
    const long rowb  = (long)b * NP1;
    float* cc  = out + 0 * plane + rowb;
    float* mc  = out + 1 * plane + rowb;
    float* fc  = out + 2 * plane + rowb;
    float* cp  = out + 3 * plane + rowb;
    float* mp  = out + 4 * plane + rowb;
    float* fp_ = out + 5 * plane + rowb;
    float* cs  = out + 6 * plane + rowb;
    float* ms  = out + 7 * plane + rowb;
    float* fs  = out + 8 * plane + rowb;
    const int b_align = b & 3;                  // row base elem offset mod 4

    // ---- scatter (stable: thread order, then element order) ----
    const int pbase = t * 8;
#pragma unroll
    for (int i = 0; i < 8; i++) {
        const int g = gv[i];
        const float v = (float)iv[i];
        const float p = (float)(pbase + i);
        if (g == 0)      { cc[off0] = v; cp[off0] = p; off0++; }
        else if (g == 1) { mc[off1] = v; mp[off1] = p; off1++; }
        else             { fc[off2] = v; fp_[off2] = p; off2++; }
    }

    // ---- vectorized EOS + PAD tails ----
    fill_tail(cc,  cnt0, CONTENT_EOS,    CONTENT_PAD,    t, b_align);
    fill_tail(cp,  cnt0, COARSE_POS_EOS, COARSE_POS_PAD, t, b_align);
    fill_tail(mc,  cnt1, CONTENT_EOS,    CONTENT_PAD,    t, b_align);
    fill_tail(mp,  cnt1, MEDIUM_POS_EOS, MEDIUM_POS_PAD, t, b_align);
    fill_tail(fc,  cnt2, CONTENT_EOS,    CONTENT_PAD,    t, b_align);
    fill_tail(fp_, cnt2, FINE_POS_EOS,   FINE_POS_PAD,   t, b_align);

    // ---- vectorized constant segment planes ----
    fill_const(cs, 0.0f, t, b_align);
    fill_const(ms, 1.0f, t, b_align);
    fill_const(fs, 2.0f, t, b_align);
}

extern "C" void kernel_launch(void* const* d_in, const int* in_sizes, int n_in,
                              void* d_out, int out_size)
{
    const int* in0 = (const int*)d_in[0];
    const int* in1 = (const int*)d_in[1];
    float* out = (float*)d_out;
    triple_grain_kernel<<<BATCH, NTHR>>>(in0, in1, out);
}

// round 9
// speedup vs baseline: 1.8025x; 1.2809x over previous
#include <cuda_runtime.h>
#include <cuda_bf16.h>

#define BATCH 512
#define NTOK  4096
#define NP1   4097
#define NTHR  512

#define CONTENT_PAD 1024.0f
#define CONTENT_EOS 1025.0f
#define COARSE_POS_PAD 128.0f
#define COARSE_POS_EOS 129.0f
#define MEDIUM_POS_PAD 256.0f
#define MEDIUM_POS_EOS 257.0f
#define FINE_POS_PAD 1024.0f
#define FINE_POS_EOS 1025.0f

// Fill indices [cnt, NP1): EOS at cnt, PAD beyond. Row base global elem
// offset is congruent to b_align (mod 4).
__device__ __forceinline__ void fill_tail(float* __restrict__ ptr, int cnt,
                                          float eos, float pad,
                                          int t, int b_align)
{
    if (t == 0) ptr[cnt] = eos;
    const int start = cnt + 1;
    int vstart = start + ((4 - ((start + b_align) & 3)) & 3);
    if (vstart > NP1) vstart = NP1;
    for (int j = start + t; j < vstart; j += NTHR) ptr[j] = pad;
    const int nvec = (NP1 - vstart) >> 2;
    const float4 p4 = make_float4(pad, pad, pad, pad);
    float4* vp = (float4*)(ptr + vstart);
    for (int c = t; c < nvec; c += NTHR) vp[c] = p4;
    const int tail = vstart + (nvec << 2);
    for (int j = tail + t; j < NP1; j += NTHR) ptr[j] = pad;
}

// Copy cnt elems from smem (sm[0..cnt)) to gmem coalesced, then EOS/PAD tail.
__device__ __forceinline__ void write_section(float* __restrict__ ptr,
                                              const float* __restrict__ sm,
                                              int cnt, float eos, float pad,
                                              int t, int b_align)
{
    int vstart = (4 - b_align) & 3;
    if (vstart > cnt) vstart = cnt;
    for (int j = t; j < vstart; j += NTHR) ptr[j] = sm[j];
    const int nvec = (cnt - vstart) >> 2;
    float4* vp = (float4*)(ptr + vstart);
    for (int c = t; c < nvec; c += NTHR) {
        const int j = vstart + (c << 2);
        vp[c] = make_float4(sm[j], sm[j + 1], sm[j + 2], sm[j + 3]);
    }
    for (int j = vstart + (nvec << 2) + t; j < cnt; j += NTHR) ptr[j] = sm[j];
    fill_tail(ptr, cnt, eos, pad, t, b_align);
}

// Fill whole row [0, NP1) with a constant, vectorized.
__device__ __forceinline__ void fill_const(float* __restrict__ ptr, float val,
                                           int t, int b_align)
{
    const int vstart = (4 - b_align) & 3;
    for (int j = t; j < vstart; j += NTHR) ptr[j] = val;
    const int nvec = (NP1 - vstart) >> 2;
    const float4 p4 = make_float4(val, val, val, val);
    float4* vp = (float4*)(ptr + vstart);
    for (int c = t; c < nvec; c += NTHR) vp[c] = p4;
    const int tail = vstart + (nvec << 2);
    for (int j = tail + t; j < NP1; j += NTHR) ptr[j] = val;
}

// Output: 9 sections, each [BATCH, NP1] float32, in tuple order:
//  0 coarse_content, 1 medium_content, 2 fine_content,
//  3 coarse_position, 4 medium_position, 5 fine_position,
//  6 coarse_segment,  7 medium_segment,  8 fine_segment
__global__ __launch_bounds__(NTHR)
void triple_grain_kernel(const int* __restrict__ in0,
                         const int* __restrict__ in1,
                         float* __restrict__ out)
{
    __shared__ float sval[NTOK];    // compacted content (classes contiguous)
    __shared__ float sposn[NTOK];   // compacted positions

    const int b = blockIdx.x;
    const int t = threadIdx.x;
    const unsigned lane = t & 31u;
    const unsigned warp = t >> 5;

    // ---- load 8 values from each input (vectorized, register-resident) ----
    const int4* a4 = (const int4*)(in0 + (long)b * NTOK);
    const int4* b4 = (const int4*)(in1 + (long)b * NTOK);
    int4 aa = a4[t * 2 + 0];
    int4 ab = a4[t * 2 + 1];
    int4 ba = b4[t * 2 + 0];
    int4 bb = b4[t * 2 + 1];
    int av[8] = {aa.x, aa.y, aa.z, aa.w, ab.x, ab.y, ab.z, ab.w};
    int bv[8] = {ba.x, ba.y, ba.z, ba.w, bb.x, bb.y, bb.z, bb.w};

    // ---- which input is grain? (grain row max <= 2) ----
    int amax = av[0];
#pragma unroll
    for (int i = 1; i < 8; i++) amax = max(amax, av[i]);
#pragma unroll
    for (int d = 16; d > 0; d >>= 1)
        amax = max(amax, __shfl_xor_sync(0xffffffffu, amax, d));

    __shared__ int smax[16];
    __shared__ int s_a_is_grain;
    if (lane == 0) smax[warp] = amax;
    __syncthreads();
    if (t == 0) {
        int m = smax[0];
#pragma unroll
        for (int i = 1; i < 16; i++) m = max(m, smax[i]);
        s_a_is_grain = (m <= 2) ? 1 : 0;
    }
    __syncthreads();
    const bool a_is_grain = (s_a_is_grain != 0);

    int gv[8], iv[8];
#pragma unroll
    for (int i = 0; i < 8; i++) {
        gv[i] = a_is_grain ? av[i] : bv[i];
        iv[i] = a_is_grain ? bv[i] : av[i];
    }

    // ---- per-thread counts of class 0 / class 1 (class 2 derived) ----
    unsigned c0 = 0, c1 = 0;
#pragma unroll
    for (int i = 0; i < 8; i++) {
        c0 += (gv[i] == 0);
        c1 += (gv[i] == 1);
    }
    const unsigned packed = c0 | (c1 << 16);

    // ---- block-wide exclusive scan of packed (16 warps) ----
    unsigned inc = packed;
#pragma unroll
    for (int d = 1; d < 32; d <<= 1) {
        unsigned n = __shfl_up_sync(0xffffffffu, inc, d);
        if (lane >= (unsigned)d) inc += n;
    }

    __shared__ unsigned warp_sums[16];
    __shared__ unsigned block_total;
    if (lane == 31) warp_sums[warp] = inc;
    __syncthreads();

    if (warp == 0 && lane < 16) {
        unsigned w = warp_sums[lane];
        unsigned wi = w;
#pragma unroll
        for (int d = 1; d < 16; d <<= 1) {
            unsigned n = __shfl_up_sync(0xffffu, wi, d);
            if (lane >= (unsigned)d) wi += n;
        }
        warp_sums[lane] = wi - w;
        if (lane == 15) block_total = wi;
    }
    __syncthreads();

    const unsigned ex = warp_sums[warp] + (inc - packed);
    const unsigned tot = block_total;

    const int cnt0 = (int)(tot & 0xFFFFu);
    const int cnt1 = (int)(tot >> 16);
    const int cnt2 = NTOK - cnt0 - cnt1;

    // within-class offsets -> absolute smem slots (classes contiguous)
    int off0 = (int)(ex & 0xFFFFu);                    // + 0
    int off1 = cnt0 + (int)(ex >> 16);                 // + cnt0
    int off2 = (cnt0 + cnt1) + (8 * t - (int)(ex & 0xFFFFu) - (int)(ex >> 16));

    // ---- scatter into SMEM (stable) ----
    const int pbase = t * 8;
#pragma unroll
    for (int i = 0; i < 8; i++) {
        const int g = gv[i];
        const float v = (float)iv[i];
        const float p = (float)(pbase + i);
        int slot;
        if (g == 0)      { slot = off0++; }
        else if (g == 1) { slot = off1++; }
        else             { slot = off2++; }
        sval[slot]  = v;
        sposn[slot] = p;
    }
    __syncthreads();

    // ---- section base pointers for this row ----
    const long plane = (long)BATCH * NP1;
    const long rowb  = (long)b * NP1;
    float* cc  = out + 0 * plane + rowb;
    float* mc  = out + 1 * plane + rowb;
    float* fc  = out + 2 * plane + rowb;
    float* cp  = out + 3 * plane + rowb;
    float* mp  = out + 4 * plane + rowb;
    float* fp_ = out + 5 * plane + rowb;
    float* cs  = out + 6 * plane + rowb;
    float* ms  = out + 7 * plane + rowb;
    float* fs  = out + 8 * plane + rowb;
    const int b_align = b & 3;

    // ---- coalesced section writes (copy + EOS/PAD tail) ----
    write_section(cc,  sval,               cnt0, CONTENT_EOS,    CONTENT_PAD,    t, b_align);
    write_section(cp,  sposn,              cnt0, COARSE_POS_EOS, COARSE_POS_PAD, t, b_align);
    write_section(mc,  sval + cnt0,        cnt1, CONTENT_EOS,    CONTENT_PAD,    t, b_align);
    write_section(mp,  sposn + cnt0,       cnt1, MEDIUM_POS_EOS, MEDIUM_POS_PAD, t, b_align);
    write_section(fc,  sval + cnt0 + cnt1, cnt2, CONTENT_EOS,    CONTENT_PAD,    t, b_align);
    write_section(fp_, sposn + cnt0 + cnt1,cnt2, FINE_POS_EOS,   FINE_POS_PAD,   t, b_align);

    // ---- constant segment planes ----
    fill_const(cs, 0.0f, t, b_align);
    fill_const(ms, 1.0f, t, b_align);
    fill_const(fs, 2.0f, t, b_align);
}

extern "C" void kernel_launch(void* const* d_in, const int* in_sizes, int n_in,
                              void* d_out, int out_size)
{
    const int* in0 = (const int*)d_in[0];
    const int* in1 = (const int*)d_in[1];
    float* out = (float*)d_out;
    triple_grain_kernel<<<BATCH, NTHR>>>(in0, in1, out);
}

// round 10
// speedup vs baseline: 1.9518x; 1.0828x over previous
#include <cuda_runtime.h>
#include <cuda_bf16.h>

#define BATCH 512
#define NTOK  4096
#define NP1   4097
#define NTHR  512

#define CONTENT_PAD 1024.0f
#define CONTENT_EOS 1025.0f
#define COARSE_POS_PAD 128.0f
#define COARSE_POS_EOS 129.0f
#define MEDIUM_POS_PAD 256.0f
#define MEDIUM_POS_EOS 257.0f
#define FINE_POS_PAD 1024.0f
#define FINE_POS_EOS 1025.0f

// Copy cnt elems from two smem arrays to two gmem planes, coalesced float4.
__device__ __forceinline__ void copy_pair(float* __restrict__ pc, float* __restrict__ pp,
                                          const float* __restrict__ sv,
                                          const float* __restrict__ sp,
                                          int cnt, int t, int b_align)
{
    int vstart = (4 - b_align) & 3;
    if (vstart > cnt) vstart = cnt;
    for (int j = t; j < vstart; j += NTHR) { pc[j] = sv[j]; pp[j] = sp[j]; }
    const int nvec = (cnt - vstart) >> 2;
    float4* c4 = (float4*)(pc + vstart);
    float4* p4 = (float4*)(pp + vstart);
    for (int c = t; c < nvec; c += NTHR) {
        const int j = vstart + (c << 2);
        c4[c] = make_float4(sv[j], sv[j+1], sv[j+2], sv[j+3]);
        p4[c] = make_float4(sp[j], sp[j+1], sp[j+2], sp[j+3]);
    }
    for (int j = vstart + (nvec << 2) + t; j < cnt; j += NTHR) {
        pc[j] = sv[j]; pp[j] = sp[j];
    }
}

// EOS at cnt, PAD beyond, for two planes sharing cnt.
__device__ __forceinline__ void tail_pair(float* __restrict__ pc, float* __restrict__ pp,
                                          int cnt, float eosC, float padC,
                                          float eosP, float padP,
                                          int t, int b_align)
{
    if (t == 0) { pc[cnt] = eosC; pp[cnt] = eosP; }
    const int start = cnt + 1;
    int vstart = start + ((4 - ((start + b_align) & 3)) & 3);
    if (vstart > NP1) vstart = NP1;
    for (int j = start + t; j < vstart; j += NTHR) { pc[j] = padC; pp[j] = padP; }
    const int nvec = (NP1 - vstart) >> 2;
    float4* c4 = (float4*)(pc + vstart);
    float4* p4 = (float4*)(pp + vstart);
    const float4 pcv = make_float4(padC, padC, padC, padC);
    const float4 ppv = make_float4(padP, padP, padP, padP);
    for (int c = t; c < nvec; c += NTHR) { c4[c] = pcv; p4[c] = ppv; }
    for (int j = vstart + (nvec << 2) + t; j < NP1; j += NTHR) {
        pc[j] = padC; pp[j] = padP;
    }
}

// Three constant planes in one loop.
__device__ __forceinline__ void fill_const3(float* __restrict__ p0, float* __restrict__ p1,
                                            float* __restrict__ p2,
                                            int t, int b_align)
{
    const int vstart = (4 - b_align) & 3;
    for (int j = t; j < vstart; j += NTHR) { p0[j] = 0.0f; p1[j] = 1.0f; p2[j] = 2.0f; }
    const int nvec = (NP1 - vstart) >> 2;
    float4* a4 = (float4*)(p0 + vstart);
    float4* b4 = (float4*)(p1 + vstart);
    float4* c4 = (float4*)(p2 + vstart);
    const float4 v0 = make_float4(0.f, 0.f, 0.f, 0.f);
    const float4 v1 = make_float4(1.f, 1.f, 1.f, 1.f);
    const float4 v2 = make_float4(2.f, 2.f, 2.f, 2.f);
    for (int c = t; c < nvec; c += NTHR) { a4[c] = v0; b4[c] = v1; c4[c] = v2; }
    const int tail = vstart + (nvec << 2);
    for (int j = tail + t; j < NP1; j += NTHR) { p0[j] = 0.0f; p1[j] = 1.0f; p2[j] = 2.0f; }
}

// Output: 9 sections, each [BATCH, NP1] float32, tuple order:
//  0 coarse_content, 1 medium_content, 2 fine_content,
//  3 coarse_position, 4 medium_position, 5 fine_position,
//  6 coarse_segment,  7 medium_segment,  8 fine_segment
__global__ __launch_bounds__(NTHR, 3)
void triple_grain_kernel(const int* __restrict__ in0,
                         const int* __restrict__ in1,
                         float* __restrict__ out)
{
    __shared__ float sval[NTOK];    // compacted content (classes contiguous)
    __shared__ float sposn[NTOK];   // compacted positions

    const int b = blockIdx.x;
    const int t = threadIdx.x;
    const unsigned lane = t & 31u;
    const unsigned warp = t >> 5;

    const int4* a4 = (const int4*)(in0 + (long)b * NTOK);
    const int4* b4 = (const int4*)(in1 + (long)b * NTOK);

    // ---- phase 1: load, compute max(in0) + counts for BOTH interpretations ----
    unsigned a0 = 0, a1 = 0, b0 = 0, b1 = 0;
    int amax = 0;
    {
        int4 xa = a4[t * 2 + 0];
        int4 xb = a4[t * 2 + 1];
        int4 ya = b4[t * 2 + 0];
        int4 yb = b4[t * 2 + 1];
        int av[8] = {xa.x, xa.y, xa.z, xa.w, xb.x, xb.y, xb.z, xb.w};
        int bv[8] = {ya.x, ya.y, ya.z, ya.w, yb.x, yb.y, yb.z, yb.w};
#pragma unroll
        for (int i = 0; i < 8; i++) {
            amax = max(amax, av[i]);
            a0 += (av[i] == 0); a1 += (av[i] == 1);
            b0 += (bv[i] == 0); b1 += (bv[i] == 1);
        }
    }
#pragma unroll
    for (int d = 16; d > 0; d >>= 1)
        amax = max(amax, __shfl_xor_sync(0xffffffffu, amax, d));

    __shared__ int smax[16];
    __shared__ int s_a_is_grain;
    if (lane == 0) smax[warp] = amax;
    __syncthreads();
    if (t == 0) {
        int m = smax[0];
#pragma unroll
        for (int i = 1; i < 16; i++) m = max(m, smax[i]);
        s_a_is_grain = (m <= 2) ? 1 : 0;
    }
    __syncthreads();
    const bool a_is_grain = (s_a_is_grain != 0);

    const unsigned packed = a_is_grain ? (a0 | (a1 << 16)) : (b0 | (b1 << 16));

    // ---- block-wide exclusive scan of packed (16 warps) ----
    unsigned inc = packed;
#pragma unroll
    for (int d = 1; d < 32; d <<= 1) {
        unsigned n = __shfl_up_sync(0xffffffffu, inc, d);
        if (lane >= (unsigned)d) inc += n;
    }

    __shared__ unsigned warp_sums[16];
    __shared__ unsigned block_total;
    if (lane == 31) warp_sums[warp] = inc;
    __syncthreads();

    if (warp == 0 && lane < 16) {
        unsigned w = warp_sums[lane];
        unsigned wi = w;
#pragma unroll
        for (int d = 1; d < 16; d <<= 1) {
            unsigned n = __shfl_up_sync(0xffffu, wi, d);
            if (lane >= (unsigned)d) wi += n;
        }
        warp_sums[lane] = wi - w;
        if (lane == 15) block_total = wi;
    }
    __syncthreads();

    const unsigned ex = warp_sums[warp] + (inc - packed);
    const unsigned tot = block_total;

    const int cnt0 = (int)(tot & 0xFFFFu);
    const int cnt1 = (int)(tot >> 16);
    const int cnt2 = NTOK - cnt0 - cnt1;

    int off0 = (int)(ex & 0xFFFFu);
    int off1 = cnt0 + (int)(ex >> 16);
    int off2 = (cnt0 + cnt1) + (8 * t - (int)(ex & 0xFFFFu) - (int)(ex >> 16));

    // ---- phase 2: reload inputs (L1/L2 hot) and scatter into SMEM ----
    {
        int4 xa = a4[t * 2 + 0];
        int4 xb = a4[t * 2 + 1];
        int4 ya = b4[t * 2 + 0];
        int4 yb = b4[t * 2 + 1];
        int av[8] = {xa.x, xa.y, xa.z, xa.w, xb.x, xb.y, xb.z, xb.w};
        int bv[8] = {ya.x, ya.y, ya.z, ya.w, yb.x, yb.y, yb.z, yb.w};
        const int pbase = t * 8;
#pragma unroll
        for (int i = 0; i < 8; i++) {
            const int g = a_is_grain ? av[i] : bv[i];
            const int v = a_is_grain ? bv[i] : av[i];
            int slot;
            if (g == 0)      { slot = off0++; }
            else if (g == 1) { slot = off1++; }
            else             { slot = off2++; }
            sval[slot]  = (float)v;
            sposn[slot] = (float)(pbase + i);
        }
    }
    __syncthreads();

    // ---- section base pointers for this row ----
    const long plane = (long)BATCH * NP1;
    const long rowb  = (long)b * NP1;
    float* cc  = out + 0 * plane + rowb;
    float* mc  = out + 1 * plane + rowb;
    float* fc  = out + 2 * plane + rowb;
    float* cp  = out + 3 * plane + rowb;
    float* mp  = out + 4 * plane + rowb;
    float* fp_ = out + 5 * plane + rowb;
    float* cs  = out + 6 * plane + rowb;
    float* ms  = out + 7 * plane + rowb;
    float* fs  = out + 8 * plane + rowb;
    const int b_align = b & 3;

    // ---- paired coalesced writes ----
    copy_pair(cc,  cp,  sval,               sposn,               cnt0, t, b_align);
    tail_pair(cc,  cp,  cnt0, CONTENT_EOS, CONTENT_PAD, COARSE_POS_EOS, COARSE_POS_PAD, t, b_align);
    copy_pair(mc,  mp,  sval + cnt0,        sposn + cnt0,        cnt1, t, b_align);
    tail_pair(mc,  mp,  cnt1, CONTENT_EOS, CONTENT_PAD, MEDIUM_POS_EOS, MEDIUM_POS_PAD, t, b_align);
    copy_pair(fc,  fp_, sval + cnt0 + cnt1, sposn + cnt0 + cnt1, cnt2, t, b_align);
    tail_pair(fc,  fp_, cnt2, CONTENT_EOS, CONTENT_PAD, FINE_POS_EOS,   FINE_POS_PAD,   t, b_align);

    fill_const3(cs, ms, fs, t, b_align);
}

extern "C" void kernel_launch(void* const* d_in, const int* in_sizes, int n_in,
                              void* d_out, int out_size)
{
    const int* in0 = (const int*)d_in[0];
    const int* in1 = (const int*)d_in[1];
    float* out = (float*)d_out;
    triple_grain_kernel<<<BATCH, NTHR>>>(in0, in1, out);
}